// round 3
// baseline (speedup 1.0000x reference)
#include <cuda_runtime.h>

// Fixed problem shapes
#define NS   4
#define NP   4096      // 64*64 pixels
#define NSZ  24        // (2*bw+1)*el = 3*8
#define CN   64
// emb channel offsets: sf(6) ce(64) mu(64) var(64) spa(2) ang(6) = 206

// Output layout (flat concat of the 5-tuple, all f32)
#define OFF_R0 0        // ref_novel_view (1,3,64,64)
#define OFF_BL 12288    // blended_img    (1,3,64,64)
#define OFF_IV 24576    // interp_view    (1,4,3,64,64)
#define OFF_WT 73728    // weight         (1,4,64,64,24)
#define OFF_CF 466944   // confs          (1,4,64,64)

// Scratch (no allocations allowed -> device globals)
__device__ float g_ce  [NS*CN*NP];   // flowRefNet features
__device__ float g_ctx [NS*CN*NP];   // ctxNet features
__device__ float g_ictx[NS*CN*NP];   // interp_ctx, layout [(s*64+k)*NP + p]
__device__ float g_psv [NS*CN*NP];   // psv_feat,   layout [(s*64+oc)*NP + p]
__device__ float g_clog[NS*NP];      // confNet logits

__device__ __forceinline__ float wsum(float v){
  #pragma unroll
  for (int o = 16; o; o >>= 1) v += __shfl_xor_sync(0xFFFFFFFFu, v, o);
  return v;
}
__device__ __forceinline__ float wmax(float v){
  #pragma unroll
  for (int o = 16; o; o >>= 1) v = fmaxf(v, __shfl_xor_sync(0xFFFFFFFFu, v, o));
  return v;
}

// ---------------------------------------------------------------------------
// K1a: flowRefNet conv  cat([sf(6), sv(3), wv(9)]) -> 64ch, 3x3 SAME, relu
// grid (32, 64, 4), block 128
// ---------------------------------------------------------------------------
__global__ void k_flow(const float* __restrict__ sf, const float* __restrict__ sv,
                       const float* __restrict__ wv, const float* __restrict__ wgt,
                       const float* __restrict__ bias){
  __shared__ float sw[18*9];
  int oc = blockIdx.y, bs = blockIdx.z;
  for (int i = threadIdx.x; i < 162; i += blockDim.x) sw[i] = wgt[oc*162 + i];
  __syncthreads();
  int p = blockIdx.x*blockDim.x + threadIdx.x;
  int y = p >> 6, x = p & 63;
  float acc = bias[oc];
  #pragma unroll 1
  for (int ic = 0; ic < 18; ic++){
    const float* src = (ic < 6) ? sf + (bs*6 + ic)*NP
                     : (ic < 9) ? sv + (bs*3 + (ic-6))*NP
                                : wv + (bs*9 + (ic-9))*NP;
    const float* w9 = sw + ic*9;
    #pragma unroll
    for (int ky = 0; ky < 3; ky++){
      int yy = y + ky - 1; if ((unsigned)yy >= 64u) continue;
      #pragma unroll
      for (int kx = 0; kx < 3; kx++){
        int xx = x + kx - 1; if ((unsigned)xx >= 64u) continue;
        acc += w9[ky*3 + kx] * src[yy*64 + xx];
      }
    }
  }
  g_ce[(bs*CN + oc)*NP + p] = fmaxf(acc, 0.f);
}

// ---------------------------------------------------------------------------
// K1b: ctxNet conv  sv(3) -> 64ch, 3x3 SAME, relu.  grid (32,64,4), block 128
// ---------------------------------------------------------------------------
__global__ void k_ctx(const float* __restrict__ sv, const float* __restrict__ wgt,
                      const float* __restrict__ bias){
  __shared__ float sw[27];
  int oc = blockIdx.y, bs = blockIdx.z;
  for (int i = threadIdx.x; i < 27; i += blockDim.x) sw[i] = wgt[oc*27 + i];
  __syncthreads();
  int p = blockIdx.x*blockDim.x + threadIdx.x;
  int y = p >> 6, x = p & 63;
  float acc = bias[oc];
  #pragma unroll
  for (int ic = 0; ic < 3; ic++){
    const float* src = sv + (bs*3 + ic)*NP;
    const float* w9  = sw + ic*9;
    #pragma unroll
    for (int ky = 0; ky < 3; ky++){
      int yy = y + ky - 1; if ((unsigned)yy >= 64u) continue;
      #pragma unroll
      for (int kx = 0; kx < 3; kx++){
        int xx = x + kx - 1; if ((unsigned)xx >= 64u) continue;
        acc += w9[ky*3 + kx] * src[yy*64 + xx];
      }
    }
  }
  g_ctx[(bs*CN + oc)*NP + p] = fmaxf(acc, 0.f);
}

// ---------------------------------------------------------------------------
// K2: fused epipolar gather + wnet logit/softmax + cnet logit + interps.
// One warp per (source,pixel); lane n (<24) owns neighbor n = e*3 + k, dy=k-1.
// grid 2048, block 256 (8 warps)
// ---------------------------------------------------------------------------
__global__ void k_epi(const float* __restrict__ sv, const float* __restrict__ sf,
                      const int*   __restrict__ nxy,
                      const float* __restrict__ spa, const float* __restrict__ ang,
                      const float* __restrict__ ww,  const float* __restrict__ wb,
                      const float* __restrict__ cw,  const float* __restrict__ cb,
                      float* __restrict__ out){
  __shared__ float s_ww[206], s_cw[206];
  for (int i = threadIdx.x; i < 206; i += blockDim.x){ s_ww[i] = ww[i]; s_cw[i] = cw[i]; }
  __syncthreads();

  int warp = threadIdx.x >> 5, lane = threadIdx.x & 31;
  int gp = blockIdx.x*8 + warp;           // 0..16383
  int bs = gp >> 12, p = gp & 4095;
  bool act = lane < NSZ;

  int idx = 0;
  if (act){
    int e = lane / 3, k = lane % 3;
    const int* q = nxy + ((bs*NP + p)*8 + e)*2;
    int xi = min(max(q[0], 0), 63);
    int yi = min(max(q[1] + (k - 1), 0), 63);
    idx = yi*64 + xi;
  }

  float lw = 0.f, lc = 0.f;       // per-neighbor parts of wnet/cnet logits
  float mvw = 0.f, mvc = 0.f;     // mu/var parts (identical on all lanes)

  // sf channels (0..5)
  #pragma unroll
  for (int j = 0; j < 6; j++){
    float v = act ? sf[(bs*6 + j)*NP + idx] : 0.f;
    lw += s_ww[j]*v;  lc += s_cw[j]*v;
  }
  // ce channels (6..69) + mu (70..133) + var (134..197)
  #pragma unroll 1
  for (int c = 0; c < CN; c++){
    float v = act ? g_ce[(bs*CN + c)*NP + idx] : 0.f;
    lw += s_ww[6 + c]*v;  lc += s_cw[6 + c]*v;
    float s1 = wsum(v), s2 = wsum(v*v);
    float mu  = s1 * (1.f/24.f);
    float var = (s2 - 24.f*mu*mu) * (1.f/23.f);
    mvw += s_ww[70 + c]*mu + s_ww[134 + c]*var;
    mvc += s_cw[70 + c]*mu + s_cw[134 + c]*var;
  }
  // spa (198..199), ang (200..205): indexed by (channel, n=lane, p)
  if (act){
    #pragma unroll
    for (int j = 0; j < 2; j++){
      float v = spa[((bs*2 + j)*NSZ + lane)*NP + p];
      lw += s_ww[198 + j]*v;  lc += s_cw[198 + j]*v;
    }
    #pragma unroll
    for (int j = 0; j < 6; j++){
      float v = ang[((bs*6 + j)*NSZ + lane)*NP + p];
      lw += s_ww[200 + j]*v;  lc += s_cw[200 + j]*v;
    }
  }
  float logit = lw + mvw + wb[0];
  float clog  = lc + mvc + cb[0];

  // softmax over neighbors
  float m  = wmax(act ? logit : -1e30f);
  float e  = act ? __expf(logit - m) : 0.f;
  float se = wsum(e);
  float wgt = e / se;
  if (act) out[OFF_WT + (bs*NP + p)*NSZ + lane] = wgt;

  // confNet logit = sum_n w[n] * cnet_logit[n]
  float cs = wsum(act ? wgt*clog : 0.f);
  if (lane == 0) g_clog[bs*NP + p] = cs;

  // interp_view (3 channels)
  #pragma unroll
  for (int c = 0; c < 3; c++){
    float v = act ? sv[(bs*3 + c)*NP + idx] : 0.f;
    float r = wsum(wgt * v);
    if (lane == 0) out[OFF_IV + (bs*3 + c)*NP + p] = r;
  }
  // interp_ctx (64 channels)
  #pragma unroll 1
  for (int c = 0; c < CN; c++){
    float v = act ? g_ctx[(bs*CN + c)*NP + idx] : 0.f;
    float r = wsum(wgt * v);
    if (lane == 0) g_ictx[(bs*CN + c)*NP + p] = r;
  }
}

// ---------------------------------------------------------------------------
// K3: conf softmax over sources + blend.  grid 16, block 256
// ---------------------------------------------------------------------------
__global__ void k_blend(float* __restrict__ out){
  int p = blockIdx.x*blockDim.x + threadIdx.x;   // 0..4095
  float cl[NS]; float m = -1e30f;
  #pragma unroll
  for (int s = 0; s < NS; s++){ cl[s] = g_clog[s*NP + p]; m = fmaxf(m, cl[s]); }
  float se = 0.f;
  #pragma unroll
  for (int s = 0; s < NS; s++){ cl[s] = __expf(cl[s] - m); se += cl[s]; }
  float inv = 1.f/se;
  float bl[3] = {0.f, 0.f, 0.f};
  #pragma unroll
  for (int s = 0; s < NS; s++){
    float cf = cl[s]*inv;
    out[OFF_CF + s*NP + p] = cf;
    #pragma unroll
    for (int c = 0; c < 3; c++)
      bl[c] += cf * out[OFF_IV + (s*3 + c)*NP + p];
  }
  #pragma unroll
  for (int c = 0; c < 3; c++) out[OFF_BL + c*NP + p] = bl[c];
}

// ---------------------------------------------------------------------------
// K4: psvNet — per-depth 3x3 conv 6->64, relu, mean over D=8.
// Input ch 0..2 = psv slice, 3..5 = blended (same for all d).
// grid (32, 64, 4), block 128
// ---------------------------------------------------------------------------
__global__ void k_psv(const float* __restrict__ psvs, const float* __restrict__ pw,
                      const float* __restrict__ pb, const float* __restrict__ out){
  __shared__ float sw[54];
  int oc = blockIdx.y, s = blockIdx.z;
  for (int i = threadIdx.x; i < 54; i += blockDim.x) sw[i] = pw[oc*54 + i];
  __syncthreads();
  int p = blockIdx.x*blockDim.x + threadIdx.x;
  int y = p >> 6, x = p & 63;

  float blpart = pb[oc];
  #pragma unroll
  for (int c = 0; c < 3; c++){
    const float* src = out + OFF_BL + c*NP;
    const float* w9  = sw + (3 + c)*9;
    #pragma unroll
    for (int ky = 0; ky < 3; ky++){
      int yy = y + ky - 1; if ((unsigned)yy >= 64u) continue;
      #pragma unroll
      for (int kx = 0; kx < 3; kx++){
        int xx = x + kx - 1; if ((unsigned)xx >= 64u) continue;
        blpart += w9[ky*3 + kx] * src[yy*64 + xx];
      }
    }
  }
  float acc = 0.f;
  #pragma unroll 1
  for (int d = 0; d < 8; d++){
    float pv = blpart;
    #pragma unroll
    for (int c = 0; c < 3; c++){
      const float* src = psvs + (((s*3 + c)*8) + d)*NP;
      const float* w9  = sw + c*9;
      #pragma unroll
      for (int ky = 0; ky < 3; ky++){
        int yy = y + ky - 1; if ((unsigned)yy >= 64u) continue;
        #pragma unroll
        for (int kx = 0; kx < 3; kx++){
          int xx = x + kx - 1; if ((unsigned)xx >= 64u) continue;
          pv += w9[ky*3 + kx] * src[yy*64 + xx];
        }
      }
    }
    acc += fmaxf(pv, 0.f);
  }
  g_psv[(s*CN + oc)*NP + p] = acc * 0.125f;
}

// ---------------------------------------------------------------------------
// K5: vref conv 515 -> 3, 3x3 SAME, no relu.
// ch 0..2 blended, 3..258 ictx, 259..514 psv_feat.  grid (32, 3), block 128
// ---------------------------------------------------------------------------
__global__ void k_vref(const float* __restrict__ vw, const float* __restrict__ vb,
                       float* __restrict__ out){
  int oc = blockIdx.y;
  int p = blockIdx.x*blockDim.x + threadIdx.x;
  int y = p >> 6, x = p & 63;
  float acc = vb[oc];
  #pragma unroll 1
  for (int ic = 0; ic < 515; ic++){
    const float* src = (ic < 3)   ? out + OFF_BL + ic*NP
                     : (ic < 259) ? g_ictx + (ic - 3)*NP
                                  : g_psv  + (ic - 259)*NP;
    const float* w9 = vw + (oc*515 + ic)*9;
    #pragma unroll
    for (int ky = 0; ky < 3; ky++){
      int yy = y + ky - 1; if ((unsigned)yy >= 64u) continue;
      #pragma unroll
      for (int kx = 0; kx < 3; kx++){
        int xx = x + kx - 1; if ((unsigned)xx >= 64u) continue;
        acc += w9[ky*3 + kx] * src[yy*64 + xx];
      }
    }
  }
  out[OFF_R0 + oc*NP + p] = acc;
}

// ---------------------------------------------------------------------------
extern "C" void kernel_launch(void* const* d_in, const int* in_sizes, int n_in,
                              void* d_out, int out_size){
  const float* sv   = (const float*)d_in[0];   // source_views    (1,4,3,64,64)
  const float* sf   = (const float*)d_in[1];   // source_flows    (1,4,3,2,64,64)
  const float* psvs = (const float*)d_in[2];   // psvs            (1,4,3,8,64,64)
  const float* wv   = (const float*)d_in[3];   // warped views    (1,4,3,3,64,64)
  // d_in[4] source_posemaps: unused by reference
  const int*   nxy  = (const int*)  d_in[5];   // neighbor_xy     (1,4,4096,8,2)
  const float* spa  = (const float*)d_in[6];   // spa_code        (1,4,2,24,4096)
  const float* ang  = (const float*)d_in[7];   // ang_code        (1,4,6,24,4096)
  // d_in[8] band_width = 1 (hardcoded)
  const float* flow_w = (const float*)d_in[9];
  const float* flow_b = (const float*)d_in[10];
  const float* ctx_w  = (const float*)d_in[11];
  const float* ctx_b  = (const float*)d_in[12];
  const float* wnet_w = (const float*)d_in[13];
  const float* wnet_b = (const float*)d_in[14];
  const float* cnet_w = (const float*)d_in[15];
  const float* cnet_b = (const float*)d_in[16];
  const float* psv_w  = (const float*)d_in[17];
  const float* psv_b  = (const float*)d_in[18];
  const float* vref_w = (const float*)d_in[19];
  const float* vref_b = (const float*)d_in[20];
  float* out = (float*)d_out;

  k_flow <<<dim3(32, 64, 4), 128>>>(sf, sv, wv, flow_w, flow_b);
  k_ctx  <<<dim3(32, 64, 4), 128>>>(sv, ctx_w, ctx_b);
  k_epi  <<<2048, 256>>>(sv, sf, nxy, spa, ang, wnet_w, wnet_b, cnet_w, cnet_b, out);
  k_blend<<<16, 256>>>(out);
  k_psv  <<<dim3(32, 64, 4), 128>>>(psvs, psv_w, psv_b, out);
  k_vref <<<dim3(32, 3), 128>>>(vref_w, vref_b, out);
}

// round 4
// speedup vs baseline: 1.5788x; 1.5788x over previous
#include <cuda_runtime.h>

// Fixed problem shapes
#define NS   4
#define NP   4096      // 64*64 pixels
#define NSZ  24        // (2*bw+1)*el = 3*8
#define CN   64

// Output layout (flat concat of the 5-tuple, all f32)
#define OFF_R0 0        // ref_novel_view (1,3,64,64)
#define OFF_BL 12288    // blended_img    (1,3,64,64)
#define OFF_IV 24576    // interp_view    (1,4,3,64,64)
#define OFF_WT 73728    // weight         (1,4,64,64,24)
#define OFF_CF 466944   // confs          (1,4,64,64)

// Scratch (no allocations allowed -> device globals)
__device__ float g_ceT [NS*NP*CN];   // flowRefNet features, PIXEL-major [s][p][c]
__device__ float g_ctxT[NS*NP*CN];   // ctxNet features,     PIXEL-major [s][p][c]
__device__ float g_vf  [NS*NP*12];   // packed per-pixel [sf0..5, sv0..2, pad3]
__device__ float g_ictx[NS*CN*NP];   // interp_ctx, channel-major [(s*64+k)*NP + p]
__device__ float g_psv [NS*CN*NP];   // psv_feat,   channel-major
__device__ float g_clog[NS*NP];      // confNet logits
__device__ float g_vpart[5*3*NP];    // vref partial sums

__device__ __forceinline__ float wsum(float v){
  #pragma unroll
  for (int o = 16; o; o >>= 1) v += __shfl_xor_sync(0xFFFFFFFFu, v, o);
  return v;
}
__device__ __forceinline__ float wmax(float v){
  #pragma unroll
  for (int o = 16; o; o >>= 1) v = fmaxf(v, __shfl_xor_sync(0xFFFFFFFFu, v, o));
  return v;
}

// ---------------------------------------------------------------------------
// K1a: flowRefNet conv  cat([sf(6), sv(3), wv(9)]) -> 64ch, relu.
// Writes PIXEL-major. grid (32, 64, 4), block 128
// ---------------------------------------------------------------------------
__global__ void k_flow(const float* __restrict__ sf, const float* __restrict__ sv,
                       const float* __restrict__ wv, const float* __restrict__ wgt,
                       const float* __restrict__ bias){
  __shared__ float sw[18*9];
  int oc = blockIdx.y, bs = blockIdx.z;
  for (int i = threadIdx.x; i < 162; i += blockDim.x) sw[i] = wgt[oc*162 + i];
  __syncthreads();
  int p = blockIdx.x*blockDim.x + threadIdx.x;
  int y = p >> 6, x = p & 63;
  float acc = bias[oc];
  #pragma unroll 1
  for (int ic = 0; ic < 18; ic++){
    const float* src = (ic < 6) ? sf + (bs*6 + ic)*NP
                     : (ic < 9) ? sv + (bs*3 + (ic-6))*NP
                                : wv + (bs*9 + (ic-9))*NP;
    const float* w9 = sw + ic*9;
    #pragma unroll
    for (int ky = 0; ky < 3; ky++){
      int yy = y + ky - 1; if ((unsigned)yy >= 64u) continue;
      #pragma unroll
      for (int kx = 0; kx < 3; kx++){
        int xx = x + kx - 1; if ((unsigned)xx >= 64u) continue;
        acc += w9[ky*3 + kx] * src[yy*64 + xx];
      }
    }
  }
  g_ceT[(bs*NP + p)*CN + oc] = fmaxf(acc, 0.f);
}

// ---------------------------------------------------------------------------
// K1b: ctxNet conv sv(3) -> 64ch, relu. PIXEL-major out. grid (32,64,4), 128
// ---------------------------------------------------------------------------
__global__ void k_ctx(const float* __restrict__ sv, const float* __restrict__ wgt,
                      const float* __restrict__ bias){
  __shared__ float sw[27];
  int oc = blockIdx.y, bs = blockIdx.z;
  for (int i = threadIdx.x; i < 27; i += blockDim.x) sw[i] = wgt[oc*27 + i];
  __syncthreads();
  int p = blockIdx.x*blockDim.x + threadIdx.x;
  int y = p >> 6, x = p & 63;
  float acc = bias[oc];
  #pragma unroll
  for (int ic = 0; ic < 3; ic++){
    const float* src = sv + (bs*3 + ic)*NP;
    const float* w9  = sw + ic*9;
    #pragma unroll
    for (int ky = 0; ky < 3; ky++){
      int yy = y + ky - 1; if ((unsigned)yy >= 64u) continue;
      #pragma unroll
      for (int kx = 0; kx < 3; kx++){
        int xx = x + kx - 1; if ((unsigned)xx >= 64u) continue;
        acc += w9[ky*3 + kx] * src[yy*64 + xx];
      }
    }
  }
  g_ctxT[(bs*NP + p)*CN + oc] = fmaxf(acc, 0.f);
}

// ---------------------------------------------------------------------------
// K1c: pack sf(6)+sv(3) per pixel into float4-friendly records. grid 64, 256
// ---------------------------------------------------------------------------
__global__ void k_pack(const float* __restrict__ sf, const float* __restrict__ sv){
  int gid = blockIdx.x*256 + threadIdx.x;     // 0..16383
  int s = gid >> 12, p = gid & 4095;
  float v[12];
  #pragma unroll
  for (int j = 0; j < 6; j++) v[j] = sf[(s*6 + j)*NP + p];
  #pragma unroll
  for (int j = 0; j < 3; j++) v[6+j] = sv[(s*3 + j)*NP + p];
  v[9] = v[10] = v[11] = 0.f;
  float4* dst = (float4*)(g_vf + gid*12);
  dst[0] = make_float4(v[0],v[1],v[2],v[3]);
  dst[1] = make_float4(v[4],v[5],v[6],v[7]);
  dst[2] = make_float4(v[8],v[9],v[10],v[11]);
}

// ---------------------------------------------------------------------------
// K2: fused epipolar gather + wnet/cnet + softmax + interps.
// One warp per (source,pixel). LANE = CHANNEL; loop over the 24 neighbors
// with coalesced 128B loads from pixel-major ceT/ctxT.
// grid 2048, block 256 (8 warps -> 8 consecutive pixels, same source)
// ---------------------------------------------------------------------------
__global__ void k_epi(const int* __restrict__ nxy,
                      const float* __restrict__ spa, const float* __restrict__ ang,
                      const float* __restrict__ ww,  const float* __restrict__ wb,
                      const float* __restrict__ cw,  const float* __restrict__ cb,
                      float* __restrict__ out){
  __shared__ float s_ww[206], s_cw[206];
  __shared__ float s_sa[8][NSZ*9];   // [pixel-in-block][n*9 + j], pad 9 vs bank conflicts
  int tid = threadIdx.x;
  for (int i = tid; i < 206; i += 256){ s_ww[i] = ww[i]; s_cw[i] = cw[i]; }

  int gp0 = blockIdx.x*8;
  int bs = gp0 >> 12, p0 = gp0 & 4095;

  // cooperative spa/ang staging: 8 j-ch x 24 n x 8 px = 1536 floats
  for (int i = tid; i < 1536; i += 256){
    int pp = i & 7;
    int n  = (i >> 3) % 24;
    int j  = i / 192;
    const float* src = (j < 2) ? spa + ((bs*2 + j)*NSZ + n)*NP
                               : ang + ((bs*6 + (j-2))*NSZ + n)*NP;
    s_sa[pp][n*9 + j] = src[p0 + pp];
  }
  __syncthreads();

  int warp = tid >> 5, lane = tid & 31;
  int p = p0 + warp;
  bool act = lane < NSZ;

  // per-neighbor index (lane n owns neighbor n = e*3 + k, dy = k-1)
  int idx = 0;
  if (act){
    int e = lane / 3, k = lane % 3;
    const int* q = nxy + ((bs*NP + p)*8 + e)*2;
    int xi = min(max(q[0], 0), 63);
    int yi = min(max(q[1] + (k - 1), 0), 63);
    idx = yi*64 + xi;
  }

  // per-neighbor scalar part of logits (sf, spa, ang) + sv for interp
  float mylogit = 0.f, myclog = 0.f;
  float sv0 = 0.f, sv1 = 0.f, sv2 = 0.f;
  if (act){
    const float4* vf = (const float4*)(g_vf + (bs*NP + idx)*12);
    float4 A = vf[0];                 // sf0..3
    float4 B = vf[1];                 // sf4, sf5, sv0, sv1
    float  C = g_vf[(bs*NP + idx)*12 + 8];   // sv2
    mylogit = A.x*s_ww[0] + A.y*s_ww[1] + A.z*s_ww[2] + A.w*s_ww[3]
            + B.x*s_ww[4] + B.y*s_ww[5];
    myclog  = A.x*s_cw[0] + A.y*s_cw[1] + A.z*s_cw[2] + A.w*s_cw[3]
            + B.x*s_cw[4] + B.y*s_cw[5];
    sv0 = B.z; sv1 = B.w; sv2 = C;
    #pragma unroll
    for (int j = 0; j < 8; j++){
      float t = s_sa[warp][lane*9 + j];
      mylogit += s_ww[198 + j]*t;
      myclog  += s_cw[198 + j]*t;
    }
  }

  // pass 1: ce gather (coalesced), per-n dot + running channel sums
  const float* ceT = g_ceT + (size_t)bs*NP*CN;
  float wwa = s_ww[6 + lane],  wwb = s_ww[38 + lane];
  float cwa = s_cw[6 + lane],  cwb = s_cw[38 + lane];
  float a0 = 0.f, a1 = 0.f, sq0 = 0.f, sq1 = 0.f;
  #pragma unroll 4
  for (int n = 0; n < NSZ; n++){
    int ix = __shfl_sync(0xFFFFFFFFu, idx, n);
    float u0 = ceT[ix*CN + lane];
    float u1 = ceT[ix*CN + 32 + lane];
    a0 += u0; sq0 += u0*u0;
    a1 += u1; sq1 += u1*u1;
    float pw = u0*wwa + u1*wwb;
    float pc = u0*cwa + u1*cwb;
    pw = wsum(pw); pc = wsum(pc);
    if (lane == n){ mylogit += pw; myclog += pc; }
  }

  // mu/var contribution (broadcast over n)
  float mu0 = a0*(1.f/24.f), mu1 = a1*(1.f/24.f);
  float vr0 = (sq0 - 24.f*mu0*mu0)*(1.f/23.f);
  float vr1 = (sq1 - 24.f*mu1*mu1)*(1.f/23.f);
  float mw = s_ww[70+lane]*mu0 + s_ww[102+lane]*mu1 + s_ww[134+lane]*vr0 + s_ww[166+lane]*vr1;
  float mc = s_cw[70+lane]*mu0 + s_cw[102+lane]*mu1 + s_cw[134+lane]*vr0 + s_cw[166+lane]*vr1;
  mw = wsum(mw); mc = wsum(mc);
  mylogit += mw + wb[0];
  myclog  += mc + cb[0];

  // softmax over neighbors
  float m  = wmax(act ? mylogit : -1e30f);
  float e  = act ? __expf(mylogit - m) : 0.f;
  float se = wsum(e);
  float wgt = e / se;
  if (act) out[OFF_WT + (bs*NP + p)*NSZ + lane] = wgt;

  // confNet logit = sum_n w_n * clog_n
  float cs = wsum(act ? wgt*myclog : 0.f);
  if (lane == 0) g_clog[bs*NP + p] = cs;

  // interp_view (3 channels)
  float r0 = wsum(act ? wgt*sv0 : 0.f);
  float r1 = wsum(act ? wgt*sv1 : 0.f);
  float r2 = wsum(act ? wgt*sv2 : 0.f);
  if (lane == 0){
    out[OFF_IV + (bs*3 + 0)*NP + p] = r0;
    out[OFF_IV + (bs*3 + 1)*NP + p] = r1;
    out[OFF_IV + (bs*3 + 2)*NP + p] = r2;
  }

  // pass 2: interp_ctx (coalesced gathers, weighted sum over neighbors)
  const float* ctxT = g_ctxT + (size_t)bs*NP*CN;
  float acc0 = 0.f, acc1 = 0.f;
  #pragma unroll 4
  for (int n = 0; n < NSZ; n++){
    int ix = __shfl_sync(0xFFFFFFFFu, idx, n);
    float wn = __shfl_sync(0xFFFFFFFFu, wgt, n);
    acc0 += wn * ctxT[ix*CN + lane];
    acc1 += wn * ctxT[ix*CN + 32 + lane];
  }
  g_ictx[(bs*CN + lane)*NP + p]      = acc0;
  g_ictx[(bs*CN + 32 + lane)*NP + p] = acc1;
}

// ---------------------------------------------------------------------------
// K3: conf softmax over sources + blend.  grid 16, block 256
// ---------------------------------------------------------------------------
__global__ void k_blend(float* __restrict__ out){
  int p = blockIdx.x*blockDim.x + threadIdx.x;   // 0..4095
  float cl[NS]; float m = -1e30f;
  #pragma unroll
  for (int s = 0; s < NS; s++){ cl[s] = g_clog[s*NP + p]; m = fmaxf(m, cl[s]); }
  float se = 0.f;
  #pragma unroll
  for (int s = 0; s < NS; s++){ cl[s] = __expf(cl[s] - m); se += cl[s]; }
  float inv = 1.f/se;
  float bl[3] = {0.f, 0.f, 0.f};
  #pragma unroll
  for (int s = 0; s < NS; s++){
    float cf = cl[s]*inv;
    out[OFF_CF + s*NP + p] = cf;
    #pragma unroll
    for (int c = 0; c < 3; c++)
      bl[c] += cf * out[OFF_IV + (s*3 + c)*NP + p];
  }
  #pragma unroll
  for (int c = 0; c < 3; c++) out[OFF_BL + c*NP + p] = bl[c];
}

// ---------------------------------------------------------------------------
// K4: psvNet — per-depth conv 6->64, relu, mean over D=8. grid (32,64,4), 128
// ---------------------------------------------------------------------------
__global__ void k_psv(const float* __restrict__ psvs, const float* __restrict__ pw,
                      const float* __restrict__ pb, const float* __restrict__ out){
  __shared__ float sw[54];
  int oc = blockIdx.y, s = blockIdx.z;
  for (int i = threadIdx.x; i < 54; i += blockDim.x) sw[i] = pw[oc*54 + i];
  __syncthreads();
  int p = blockIdx.x*blockDim.x + threadIdx.x;
  int y = p >> 6, x = p & 63;

  float blpart = pb[oc];
  #pragma unroll
  for (int c = 0; c < 3; c++){
    const float* src = out + OFF_BL + c*NP;
    const float* w9  = sw + (3 + c)*9;
    #pragma unroll
    for (int ky = 0; ky < 3; ky++){
      int yy = y + ky - 1; if ((unsigned)yy >= 64u) continue;
      #pragma unroll
      for (int kx = 0; kx < 3; kx++){
        int xx = x + kx - 1; if ((unsigned)xx >= 64u) continue;
        blpart += w9[ky*3 + kx] * src[yy*64 + xx];
      }
    }
  }
  float acc = 0.f;
  #pragma unroll 1
  for (int d = 0; d < 8; d++){
    float pv = blpart;
    #pragma unroll
    for (int c = 0; c < 3; c++){
      const float* src = psvs + (((s*3 + c)*8) + d)*NP;
      const float* w9  = sw + c*9;
      #pragma unroll
      for (int ky = 0; ky < 3; ky++){
        int yy = y + ky - 1; if ((unsigned)yy >= 64u) continue;
        #pragma unroll
        for (int kx = 0; kx < 3; kx++){
          int xx = x + kx - 1; if ((unsigned)xx >= 64u) continue;
          pv += w9[ky*3 + kx] * src[yy*64 + xx];
        }
      }
    }
    acc += fmaxf(pv, 0.f);
  }
  g_psv[(s*CN + oc)*NP + p] = acc * 0.125f;
}

// ---------------------------------------------------------------------------
// K5: vref conv 515 -> 3, split into 5 ic-chunks for occupancy.
// grid (32, 3, 5), block 128.  Finalize sums the 5 partials.
// ---------------------------------------------------------------------------
__global__ void k_vrefp(const float* __restrict__ vw, const float* __restrict__ vb,
                        const float* __restrict__ out){
  __shared__ float sw[103*9];
  int oc = blockIdx.y, z = blockIdx.z;
  int ic0 = z*103;
  for (int i = threadIdx.x; i < 927; i += 128) sw[i] = vw[(oc*515 + ic0)*9 + i];
  __syncthreads();
  int p = blockIdx.x*blockDim.x + threadIdx.x;
  int y = p >> 6, x = p & 63;
  float acc = (z == 0) ? vb[oc] : 0.f;
  #pragma unroll 1
  for (int il = 0; il < 103; il++){
    int ic = ic0 + il;
    const float* src = (ic < 3)   ? out + OFF_BL + ic*NP
                     : (ic < 259) ? g_ictx + (ic - 3)*NP
                                  : g_psv  + (ic - 259)*NP;
    const float* w9 = sw + il*9;
    #pragma unroll
    for (int ky = 0; ky < 3; ky++){
      int yy = y + ky - 1; if ((unsigned)yy >= 64u) continue;
      #pragma unroll
      for (int kx = 0; kx < 3; kx++){
        int xx = x + kx - 1; if ((unsigned)xx >= 64u) continue;
        acc += w9[ky*3 + kx] * src[yy*64 + xx];
      }
    }
  }
  g_vpart[(z*3 + oc)*NP + p] = acc;
}

__global__ void k_vfin(float* __restrict__ out){
  int i = blockIdx.x*256 + threadIdx.x;   // 0..12287
  float a = 0.f;
  #pragma unroll
  for (int z = 0; z < 5; z++) a += g_vpart[z*3*NP + i];
  out[OFF_R0 + i] = a;
}

// ---------------------------------------------------------------------------
extern "C" void kernel_launch(void* const* d_in, const int* in_sizes, int n_in,
                              void* d_out, int out_size){
  const float* sv   = (const float*)d_in[0];   // source_views    (1,4,3,64,64)
  const float* sf   = (const float*)d_in[1];   // source_flows    (1,4,3,2,64,64)
  const float* psvs = (const float*)d_in[2];   // psvs            (1,4,3,8,64,64)
  const float* wv   = (const float*)d_in[3];   // warped views    (1,4,3,3,64,64)
  const int*   nxy  = (const int*)  d_in[5];   // neighbor_xy     (1,4,4096,8,2)
  const float* spa  = (const float*)d_in[6];   // spa_code        (1,4,2,24,4096)
  const float* ang  = (const float*)d_in[7];   // ang_code        (1,4,6,24,4096)
  const float* flow_w = (const float*)d_in[9];
  const float* flow_b = (const float*)d_in[10];
  const float* ctx_w  = (const float*)d_in[11];
  const float* ctx_b  = (const float*)d_in[12];
  const float* wnet_w = (const float*)d_in[13];
  const float* wnet_b = (const float*)d_in[14];
  const float* cnet_w = (const float*)d_in[15];
  const float* cnet_b = (const float*)d_in[16];
  const float* psv_w  = (const float*)d_in[17];
  const float* psv_b  = (const float*)d_in[18];
  const float* vref_w = (const float*)d_in[19];
  const float* vref_b = (const float*)d_in[20];
  float* out = (float*)d_out;

  k_flow <<<dim3(32, 64, 4), 128>>>(sf, sv, wv, flow_w, flow_b);
  k_ctx  <<<dim3(32, 64, 4), 128>>>(sv, ctx_w, ctx_b);
  k_pack <<<64, 256>>>(sf, sv);
  k_epi  <<<2048, 256>>>(nxy, spa, ang, wnet_w, wnet_b, cnet_w, cnet_b, out);
  k_blend<<<16, 256>>>(out);
  k_psv  <<<dim3(32, 64, 4), 128>>>(psvs, psv_w, psv_b, out);
  k_vrefp<<<dim3(32, 3, 5), 128>>>(vref_w, vref_b, out);
  k_vfin <<<48, 256>>>(out);
}

// round 5
// speedup vs baseline: 3.8544x; 2.4414x over previous
#include <cuda_runtime.h>

#define NS   4
#define NP   4096      // 64*64 pixels
#define NSZ  24        // (2*bw+1)*el
#define CN   64

// Output layout (flat concat of the 5-tuple, f32)
#define OFF_R0 0
#define OFF_BL 12288
#define OFF_IV 24576
#define OFF_WT 73728
#define OFF_CF 466944

#define VCHUNK 24                       // vref ic-chunk size
#define NVCH   22                       // ceil(515/24)

// Scratch
__device__ float  g_ceT [NS*NP*CN];     // flow features, pixel-major [s][p][c]
__device__ float  g_ctxT[NS*NP*CN];     // ctx features,  pixel-major
__device__ float4 g_rec [NS*NP];        // {dotW(oc0..31), dotC, sv0, sv1}
__device__ float4 g_rec2[NS*NP];        // {dotW(oc32..63 + sf), dotC, sv2, 0}
__device__ float  g_ictx[NS*CN*NP];     // interp_ctx, channel-major
__device__ float  g_psv [NS*CN*NP];     // psv_feat,   channel-major
__device__ float  g_clog[NS*NP];
__device__ float  g_vpart[NVCH*3*NP];

__device__ __forceinline__ float wsum(float v){
  #pragma unroll
  for (int o = 16; o; o >>= 1) v += __shfl_xor_sync(0xFFFFFFFFu, v, o);
  return v;
}
__device__ __forceinline__ float wmax(float v){
  #pragma unroll
  for (int o = 16; o; o >>= 1) v = fmaxf(v, __shfl_xor_sync(0xFFFFFFFFu, v, o));
  return v;
}

// ---------------------------------------------------------------------------
// K1a: flowRefNet conv 18->64, relu, pixel-major out + per-pixel dot record.
// grid (16 row-chunks, 2 oc-halves, 4 sources), block 256 (4 rows x 64 cols).
// Tile: rows r0-1..r0+4 (6) x cols -1..64 (66), zero-padded in smem.
// ---------------------------------------------------------------------------
__global__ void __launch_bounds__(256) k_flow(
    const float* __restrict__ sf, const float* __restrict__ sv,
    const float* __restrict__ wv, const float* __restrict__ wgt,
    const float* __restrict__ bias,
    const float* __restrict__ ww, const float* __restrict__ cw){
  __shared__ float s_in[18*396];        // 18 ch x 6 x 66
  __shared__ float s_w[256*17];         // union: weight chunk (2592) / out stage (padded)
  __shared__ float s_wc[140];           // ww[0..70) , cw[0..70)
  int rc = blockIdx.x, half = blockIdx.y, bs = blockIdx.z;
  int tid = threadIdx.x, r0 = rc*4;

  for (int i = tid; i < 18*396; i += 256){
    int c = i/396, rem = i - c*396, ry = rem/66, rx = rem - ry*66;
    int gy = r0 - 1 + ry, gx = rx - 1;
    float v = 0.f;
    if ((unsigned)gy < 64u && (unsigned)gx < 64u){
      const float* src = (c < 6) ? sf + (bs*6 + c)*NP
                       : (c < 9) ? sv + (bs*3 + (c-6))*NP
                                 : wv + (bs*9 + (c-9))*NP;
      v = src[gy*64 + gx];
    }
    s_in[i] = v;
  }
  for (int i = tid; i < 140; i += 256) s_wc[i] = (i < 70) ? ww[i] : cw[i-70];
  __syncthreads();

  int ly = tid >> 6, lx = tid & 63;
  int p = (r0 + ly)*64 + lx;
  float dW = 0.f, dC = 0.f;

  #pragma unroll 1
  for (int sub = 0; sub < 2; sub++){
    int oc0 = half*32 + sub*16;
    if (sub) __syncthreads();
    for (int i = tid; i < 16*162; i += 256) s_w[i] = wgt[oc0*162 + i];
    __syncthreads();
    float acc[16];
    #pragma unroll
    for (int j = 0; j < 16; j++) acc[j] = bias[oc0 + j];
    #pragma unroll 1
    for (int c = 0; c < 18; c++){
      const float* cin = s_in + c*396 + ly*66 + lx;
      float v[9];
      #pragma unroll
      for (int ky = 0; ky < 3; ky++)
        #pragma unroll
        for (int kx = 0; kx < 3; kx++) v[ky*3+kx] = cin[ky*66 + kx];
      const float* wr = s_w + c*9;
      #pragma unroll
      for (int j = 0; j < 16; j++){
        const float* wj = wr + j*162;
        #pragma unroll
        for (int t = 0; t < 9; t++) acc[j] = fmaf(wj[t], v[t], acc[j]);
      }
    }
    __syncthreads();
    #pragma unroll
    for (int j = 0; j < 16; j++){
      float r = fmaxf(acc[j], 0.f);
      dW = fmaf(s_wc[6 + oc0 + j],      r, dW);
      dC = fmaf(s_wc[70 + 6 + oc0 + j], r, dC);
      s_w[tid*17 + j] = r;
    }
    __syncthreads();
    for (int i = tid; i < 4096; i += 256){
      int pl = i >> 4, j = i & 15;
      g_ceT[(bs*NP + r0*64 + pl)*64 + oc0 + j] = s_w[pl*17 + j];
    }
  }

  // record epilogue: center taps of sf/sv from smem
  int cofs = (ly+1)*66 + (lx+1);
  if (half == 0){
    float sv0 = s_in[6*396 + cofs], sv1 = s_in[7*396 + cofs];
    g_rec[bs*NP + p] = make_float4(dW, dC, sv0, sv1);
  } else {
    #pragma unroll
    for (int j = 0; j < 6; j++){
      float t = s_in[j*396 + cofs];
      dW = fmaf(s_wc[j], t, dW);
      dC = fmaf(s_wc[70 + j], t, dC);
    }
    float sv2 = s_in[8*396 + cofs];
    g_rec2[bs*NP + p] = make_float4(dW, dC, sv2, 0.f);
  }
}

// ---------------------------------------------------------------------------
// K1b: ctxNet conv 3->64, relu, pixel-major. grid (16,2,4), block 256
// ---------------------------------------------------------------------------
__global__ void __launch_bounds__(256) k_ctx(
    const float* __restrict__ sv, const float* __restrict__ wgt,
    const float* __restrict__ bias){
  __shared__ float s_in[3*396];
  __shared__ float s_w[32*27];
  __shared__ float s_out[256*33];
  int rc = blockIdx.x, half = blockIdx.y, bs = blockIdx.z;
  int tid = threadIdx.x, r0 = rc*4;
  int oc0 = half*32;

  for (int i = tid; i < 3*396; i += 256){
    int c = i/396, rem = i - c*396, ry = rem/66, rx = rem - ry*66;
    int gy = r0 - 1 + ry, gx = rx - 1;
    s_in[i] = ((unsigned)gy < 64u && (unsigned)gx < 64u)
              ? sv[(bs*3 + c)*NP + gy*64 + gx] : 0.f;
  }
  for (int i = tid; i < 864; i += 256) s_w[i] = wgt[oc0*27 + i];
  __syncthreads();

  int ly = tid >> 6, lx = tid & 63;
  float acc[32];
  #pragma unroll
  for (int j = 0; j < 32; j++) acc[j] = bias[oc0 + j];
  #pragma unroll
  for (int c = 0; c < 3; c++){
    const float* cin = s_in + c*396 + ly*66 + lx;
    float v[9];
    #pragma unroll
    for (int ky = 0; ky < 3; ky++)
      #pragma unroll
      for (int kx = 0; kx < 3; kx++) v[ky*3+kx] = cin[ky*66 + kx];
    #pragma unroll
    for (int j = 0; j < 32; j++){
      const float* wj = s_w + j*27 + c*9;
      #pragma unroll
      for (int t = 0; t < 9; t++) acc[j] = fmaf(wj[t], v[t], acc[j]);
    }
  }
  #pragma unroll
  for (int j = 0; j < 32; j++) s_out[tid*33 + j] = fmaxf(acc[j], 0.f);
  __syncthreads();
  for (int i = tid; i < 8192; i += 256){
    int pl = i >> 5, j = i & 31;
    g_ctxT[(bs*NP + r0*64 + pl)*64 + oc0 + j] = s_out[pl*33 + j];
  }
}

// ---------------------------------------------------------------------------
// K2: fused epipolar gather + logits + softmax + interps.
// One warp per (source,pixel); lane = channel for the gather loops.
// grid 2048, block 256
// ---------------------------------------------------------------------------
__global__ void __launch_bounds__(256) k_epi(
    const int* __restrict__ nxy,
    const float* __restrict__ spa, const float* __restrict__ ang,
    const float* __restrict__ ww,  const float* __restrict__ wb,
    const float* __restrict__ cw,  const float* __restrict__ cb,
    float* __restrict__ out){
  __shared__ float s_ww[206], s_cw[206];
  __shared__ float s_sa[8][NSZ*9];
  int tid = threadIdx.x;
  for (int i = tid; i < 206; i += 256){ s_ww[i] = ww[i]; s_cw[i] = cw[i]; }

  int gp0 = blockIdx.x*8;
  int bs = gp0 >> 12, p0 = gp0 & 4095;

  for (int i = tid; i < 1536; i += 256){
    int pp = i & 7;
    int n  = (i >> 3) % 24;
    int j  = i / 192;
    const float* src = (j < 2) ? spa + ((bs*2 + j)*NSZ + n)*NP
                               : ang + ((bs*6 + (j-2))*NSZ + n)*NP;
    s_sa[pp][n*9 + j] = src[p0 + pp];
  }
  __syncthreads();

  int warp = tid >> 5, lane = tid & 31;
  int p = p0 + warp;
  bool act = lane < NSZ;

  int idx = 0;
  if (act){
    int e = lane / 3, k = lane % 3;
    const int* q = nxy + ((bs*NP + p)*8 + e)*2;
    int xi = min(max(q[0], 0), 63);
    int yi = min(max(q[1] + (k - 1), 0), 63);
    idx = yi*64 + xi;
  }

  float mylogit = 0.f, myclog = 0.f, sv0 = 0.f, sv1 = 0.f, sv2 = 0.f;
  if (act){
    float4 A = g_rec [bs*NP + idx];
    float4 B = g_rec2[bs*NP + idx];
    mylogit = A.x + B.x;  myclog = A.y + B.y;
    sv0 = A.z; sv1 = A.w; sv2 = B.z;
    #pragma unroll
    for (int j = 0; j < 8; j++){
      float t = s_sa[warp][lane*9 + j];
      mylogit = fmaf(s_ww[198 + j], t, mylogit);
      myclog  = fmaf(s_cw[198 + j], t, myclog);
    }
  }

  // per-channel sums over 24 neighbors (no in-loop reductions)
  const float* ceT = g_ceT + (size_t)bs*NP*CN;
  float a0 = 0.f, a1 = 0.f, sq0 = 0.f, sq1 = 0.f;
  #pragma unroll 4
  for (int n = 0; n < NSZ; n++){
    int ix = __shfl_sync(0xFFFFFFFFu, idx, n);
    float u0 = ceT[ix*CN + lane];
    float u1 = ceT[ix*CN + 32 + lane];
    a0 += u0; sq0 = fmaf(u0, u0, sq0);
    a1 += u1; sq1 = fmaf(u1, u1, sq1);
  }
  float mu0 = a0*(1.f/24.f), mu1 = a1*(1.f/24.f);
  float vr0 = (sq0 - 24.f*mu0*mu0)*(1.f/23.f);
  float vr1 = (sq1 - 24.f*mu1*mu1)*(1.f/23.f);
  float mw = s_ww[70+lane]*mu0 + s_ww[102+lane]*mu1 + s_ww[134+lane]*vr0 + s_ww[166+lane]*vr1;
  float mc = s_cw[70+lane]*mu0 + s_cw[102+lane]*mu1 + s_cw[134+lane]*vr0 + s_cw[166+lane]*vr1;
  mw = wsum(mw); mc = wsum(mc);
  mylogit += mw + wb[0];
  myclog  += mc + cb[0];

  // softmax over neighbors
  float m  = wmax(act ? mylogit : -1e30f);
  float e  = act ? __expf(mylogit - m) : 0.f;
  float se = wsum(e);
  float wgt = e / se;
  if (act) out[OFF_WT + (bs*NP + p)*NSZ + lane] = wgt;

  float cs = wsum(act ? wgt*myclog : 0.f);
  if (lane == 0) g_clog[bs*NP + p] = cs;

  float r0 = wsum(act ? wgt*sv0 : 0.f);
  float r1 = wsum(act ? wgt*sv1 : 0.f);
  float r2 = wsum(act ? wgt*sv2 : 0.f);
  if (lane == 0){
    out[OFF_IV + (bs*3 + 0)*NP + p] = r0;
    out[OFF_IV + (bs*3 + 1)*NP + p] = r1;
    out[OFF_IV + (bs*3 + 2)*NP + p] = r2;
  }

  // interp_ctx
  const float* ctxT = g_ctxT + (size_t)bs*NP*CN;
  float acc0 = 0.f, acc1 = 0.f;
  #pragma unroll 4
  for (int n = 0; n < NSZ; n++){
    int ix = __shfl_sync(0xFFFFFFFFu, idx, n);
    float wn = __shfl_sync(0xFFFFFFFFu, wgt, n);
    acc0 = fmaf(wn, ctxT[ix*CN + lane], acc0);
    acc1 = fmaf(wn, ctxT[ix*CN + 32 + lane], acc1);
  }
  g_ictx[(bs*CN + lane)*NP + p]      = acc0;
  g_ictx[(bs*CN + 32 + lane)*NP + p] = acc1;
}

// ---------------------------------------------------------------------------
// K3: conf softmax over sources + blend.  grid 16, block 256
// ---------------------------------------------------------------------------
__global__ void k_blend(float* __restrict__ out){
  int p = blockIdx.x*blockDim.x + threadIdx.x;
  float cl[NS]; float m = -1e30f;
  #pragma unroll
  for (int s = 0; s < NS; s++){ cl[s] = g_clog[s*NP + p]; m = fmaxf(m, cl[s]); }
  float se = 0.f;
  #pragma unroll
  for (int s = 0; s < NS; s++){ cl[s] = __expf(cl[s] - m); se += cl[s]; }
  float inv = 1.f/se;
  float bl[3] = {0.f, 0.f, 0.f};
  #pragma unroll
  for (int s = 0; s < NS; s++){
    float cf = cl[s]*inv;
    out[OFF_CF + s*NP + p] = cf;
    #pragma unroll
    for (int c = 0; c < 3; c++)
      bl[c] = fmaf(cf, out[OFF_IV + (s*3 + c)*NP + p], bl[c]);
  }
  #pragma unroll
  for (int c = 0; c < 3; c++) out[OFF_BL + c*NP + p] = bl[c];
}

// ---------------------------------------------------------------------------
// K4: psvNet conv 6->64 per depth, relu, mean over D=8.
// grid (16,2,4), block 256. smem-tiled, branch-free.
// ---------------------------------------------------------------------------
__global__ void __launch_bounds__(256) k_psv(
    const float* __restrict__ psvs, const float* __restrict__ pw,
    const float* __restrict__ pb, const float* __restrict__ out){
  __shared__ float s_bl[3*396];
  __shared__ float s_ps[24*396];        // [(c*8+d)][396]
  __shared__ float s_w[16*54];
  int rc = blockIdx.x, half = blockIdx.y, bs = blockIdx.z;
  int tid = threadIdx.x, r0 = rc*4;

  for (int i = tid; i < 3*396; i += 256){
    int c = i/396, rem = i - c*396, ry = rem/66, rx = rem - ry*66;
    int gy = r0 - 1 + ry, gx = rx - 1;
    s_bl[i] = ((unsigned)gy < 64u && (unsigned)gx < 64u)
              ? out[OFF_BL + c*NP + gy*64 + gx] : 0.f;
  }
  for (int i = tid; i < 24*396; i += 256){
    int cd = i/396, rem = i - cd*396, ry = rem/66, rx = rem - ry*66;
    int c = cd >> 3, d = cd & 7;
    int gy = r0 - 1 + ry, gx = rx - 1;
    s_ps[i] = ((unsigned)gy < 64u && (unsigned)gx < 64u)
              ? psvs[(((bs*3 + c)*8) + d)*NP + gy*64 + gx] : 0.f;
  }

  int ly = tid >> 6, lx = tid & 63;
  int p = (r0 + ly)*64 + lx;

  #pragma unroll 1
  for (int sub = 0; sub < 2; sub++){
    int oc0 = half*32 + sub*16;
    if (sub) __syncthreads();
    for (int i = tid; i < 864; i += 256) s_w[i] = pw[oc0*54 + i];
    __syncthreads();

    float blp[16];
    #pragma unroll
    for (int j = 0; j < 16; j++) blp[j] = pb[oc0 + j];
    #pragma unroll
    for (int c = 0; c < 3; c++){
      const float* cin = s_bl + c*396 + ly*66 + lx;
      float v[9];
      #pragma unroll
      for (int ky = 0; ky < 3; ky++)
        #pragma unroll
        for (int kx = 0; kx < 3; kx++) v[ky*3+kx] = cin[ky*66 + kx];
      #pragma unroll
      for (int j = 0; j < 16; j++){
        const float* wj = s_w + j*54 + (3 + c)*9;
        #pragma unroll
        for (int t = 0; t < 9; t++) blp[j] = fmaf(wj[t], v[t], blp[j]);
      }
    }
    float oacc[16];
    #pragma unroll
    for (int j = 0; j < 16; j++) oacc[j] = 0.f;
    #pragma unroll 1
    for (int d = 0; d < 8; d++){
      float pv[16];
      #pragma unroll
      for (int j = 0; j < 16; j++) pv[j] = blp[j];
      #pragma unroll
      for (int c = 0; c < 3; c++){
        const float* cin = s_ps + (c*8 + d)*396 + ly*66 + lx;
        float v[9];
        #pragma unroll
        for (int ky = 0; ky < 3; ky++)
          #pragma unroll
          for (int kx = 0; kx < 3; kx++) v[ky*3+kx] = cin[ky*66 + kx];
        #pragma unroll
        for (int j = 0; j < 16; j++){
          const float* wj = s_w + j*54 + c*9;
          #pragma unroll
          for (int t = 0; t < 9; t++) pv[j] = fmaf(wj[t], v[t], pv[j]);
        }
      }
      #pragma unroll
      for (int j = 0; j < 16; j++) oacc[j] += fmaxf(pv[j], 0.f);
    }
    #pragma unroll
    for (int j = 0; j < 16; j++)
      g_psv[(bs*CN + oc0 + j)*NP + p] = oacc[j] * 0.125f;
  }
}

// ---------------------------------------------------------------------------
// K5: vref conv 515->3, ic-chunked (24), smem-tiled. grid (16, 22), block 256
// ---------------------------------------------------------------------------
__global__ void __launch_bounds__(256) k_vref(
    const float* __restrict__ vw, const float* __restrict__ vb,
    const float* __restrict__ out){
  __shared__ float s_in[VCHUNK*396];
  __shared__ float s_w[3*216];
  int rc = blockIdx.x, z = blockIdx.y;
  int tid = threadIdx.x, r0 = rc*4;
  int ic0 = z*VCHUNK;
  int nch = min(VCHUNK, 515 - ic0);

  for (int i = tid; i < nch*396; i += 256){
    int c = i/396, rem = i - c*396, ry = rem/66, rx = rem - ry*66;
    int ic = ic0 + c;
    int gy = r0 - 1 + ry, gx = rx - 1;
    float v = 0.f;
    if ((unsigned)gy < 64u && (unsigned)gx < 64u){
      const float* src = (ic < 3)   ? out + OFF_BL + ic*NP
                       : (ic < 259) ? g_ictx + (ic - 3)*NP
                                    : g_psv  + (ic - 259)*NP;
      v = src[gy*64 + gx];
    }
    s_in[i] = v;
  }
  for (int i = tid; i < 3*nch*9; i += 256){
    int oc = i / (nch*9), rem = i - oc*(nch*9);
    s_w[oc*216 + rem] = vw[(oc*515 + ic0)*9 + rem];
  }
  __syncthreads();

  int ly = tid >> 6, lx = tid & 63;
  int p = (r0 + ly)*64 + lx;
  float acc[3];
  #pragma unroll
  for (int oc = 0; oc < 3; oc++) acc[oc] = (z == 0) ? vb[oc] : 0.f;
  #pragma unroll 1
  for (int c = 0; c < nch; c++){
    const float* cin = s_in + c*396 + ly*66 + lx;
    float v[9];
    #pragma unroll
    for (int ky = 0; ky < 3; ky++)
      #pragma unroll
      for (int kx = 0; kx < 3; kx++) v[ky*3+kx] = cin[ky*66 + kx];
    #pragma unroll
    for (int oc = 0; oc < 3; oc++){
      const float* wj = s_w + oc*216 + c*9;
      #pragma unroll
      for (int t = 0; t < 9; t++) acc[oc] = fmaf(wj[t], v[t], acc[oc]);
    }
  }
  #pragma unroll
  for (int oc = 0; oc < 3; oc++) g_vpart[(z*3 + oc)*NP + p] = acc[oc];
}

__global__ void k_vfin(float* __restrict__ out){
  int i = blockIdx.x*256 + threadIdx.x;   // 0..12287
  float a = 0.f;
  #pragma unroll
  for (int z = 0; z < NVCH; z++) a += g_vpart[z*3*NP + i];
  out[OFF_R0 + i] = a;
}

// ---------------------------------------------------------------------------
extern "C" void kernel_launch(void* const* d_in, const int* in_sizes, int n_in,
                              void* d_out, int out_size){
  const float* sv   = (const float*)d_in[0];
  const float* sf   = (const float*)d_in[1];
  const float* psvs = (const float*)d_in[2];
  const float* wv   = (const float*)d_in[3];
  const int*   nxy  = (const int*)  d_in[5];
  const float* spa  = (const float*)d_in[6];
  const float* ang  = (const float*)d_in[7];
  const float* flow_w = (const float*)d_in[9];
  const float* flow_b = (const float*)d_in[10];
  const float* ctx_w  = (const float*)d_in[11];
  const float* ctx_b  = (const float*)d_in[12];
  const float* wnet_w = (const float*)d_in[13];
  const float* wnet_b = (const float*)d_in[14];
  const float* cnet_w = (const float*)d_in[15];
  const float* cnet_b = (const float*)d_in[16];
  const float* psv_w  = (const float*)d_in[17];
  const float* psv_b  = (const float*)d_in[18];
  const float* vref_w = (const float*)d_in[19];
  const float* vref_b = (const float*)d_in[20];
  float* out = (float*)d_out;

  k_flow <<<dim3(16, 2, 4), 256>>>(sf, sv, wv, flow_w, flow_b, wnet_w, cnet_w);
  k_ctx  <<<dim3(16, 2, 4), 256>>>(sv, ctx_w, ctx_b);
  k_epi  <<<2048, 256>>>(nxy, spa, ang, wnet_w, wnet_b, cnet_w, cnet_b, out);
  k_blend<<<16, 256>>>(out);
  k_psv  <<<dim3(16, 2, 4), 256>>>(psvs, psv_w, psv_b, out);
  k_vref <<<dim3(16, NVCH), 256>>>(vref_w, vref_b, out);
  k_vfin <<<48, 256>>>(out);
}